// round 10
// baseline (speedup 1.0000x reference)
#include <cuda_runtime.h>
#include <cuda_fp16.h>
#include <cstdint>

// Problem constants
#define BB 8
#define CC 512
#define OO 512
#define KTOT 2048          // CC * 4 taps
#define KC 64              // K per chunk
#define NCHUNKS 32         // KTOT / KC
#define LDR 144            // smem row stride (bytes): 128B data + 16B pad
#define NTILES 1024        // 8 nx * 4 oy * 32 (b*4+p)
#define GRID_MMA 304       // persistent CTAs (2 per SM, 152 SMs)

// Scratch (no allocation allowed -> device globals)
__device__ float g_smod[BB * CC];                    // 1 + style @ fc_w^T + fc_b
__device__ float g_d[BB * OO];                       // demod scale
__device__ float g_w2t[CC * OO];                     // sum_k conv_w^2, [c][o]
__device__ __align__(16) __half g_wh[4 * OO * KTOT]; // [p][o][k] fp16 parity weights
__device__ __align__(16) __half g_xs[BB * CC * 1024];// fp16(x * smod) [b][c][pix]
__device__ unsigned g_ctr;                           // persistent work counter

// ---------------------------------------------------------------------------
__device__ __forceinline__ uint32_t smem_u32(const void* p) {
    uint32_t a;
    asm("{ .reg .u64 t; cvta.to.shared.u64 t, %1; cvt.u32.u64 %0, t; }"
        : "=r"(a) : "l"(p));
    return a;
}
#define CP_ASYNC16(dst, src) \
    asm volatile("cp.async.cg.shared.global [%0], [%1], 16;\n" \
                 :: "r"(dst), "l"(__cvta_generic_to_global(src)))
#define CP_COMMIT()  asm volatile("cp.async.commit_group;\n" ::: "memory")
#define CP_WAIT0()   asm volatile("cp.async.wait_group 0;\n" ::: "memory")

#define LDMATRIX_X4(r, addr) \
    asm volatile("ldmatrix.sync.aligned.m8n8.x4.shared.b16 {%0,%1,%2,%3}, [%4];\n" \
                 : "=r"((r)[0]), "=r"((r)[1]), "=r"((r)[2]), "=r"((r)[3]) : "r"(addr))

#define MMA16816(d, a, b0v, b1v) \
    asm volatile("mma.sync.aligned.m16n8k16.row.col.f32.f16.f16.f32 " \
                 "{%0,%1,%2,%3},{%4,%5,%6,%7},{%8,%9},{%0,%1,%2,%3};\n" \
                 : "+f"((d)[0]), "+f"((d)[1]), "+f"((d)[2]), "+f"((d)[3]) \
                 : "r"((a)[0]), "r"((a)[1]), "r"((a)[2]), "r"((a)[3]), \
                   "r"(b0v), "r"(b1v))

// ---------------------------------------------------------------------------
// s[b][c] = 1 + fc_b[c] + sum_k style[b][k] * fc_w[c][k]
__global__ void k_style(const float* __restrict__ style,
                        const float* __restrict__ fc_w,
                        const float* __restrict__ fc_b) {
    __shared__ float ss[512];
    int b = blockIdx.x;
    int c = threadIdx.x;
    ss[c] = style[b * 512 + c];
    __syncthreads();
    const float4* wrow = (const float4*)(fc_w + (size_t)c * 512);
    float acc = 0.f;
#pragma unroll 4
    for (int k = 0; k < 128; k++) {
        float4 w4 = wrow[k];
        acc += w4.x * ss[4 * k + 0] + w4.y * ss[4 * k + 1]
             + w4.z * ss[4 * k + 2] + w4.w * ss[4 * k + 3];
    }
    g_smod[b * 512 + c] = acc + fc_b[c] + 1.0f;
}

// ---------------------------------------------------------------------------
// Per (o,c): W2^T and 4-parity combined 2x2 stencil weights (fp16).
// Layout g_wh: [p][o][k], k = c*4 + j*2 + i.
__global__ void k_weff(const float* __restrict__ conv_w) {
    int t = blockIdx.x * 256 + threadIdx.x;   // 262144 threads
    int o = t & 511;
    int c = t >> 9;
    const float* wp = conv_w + ((size_t)o * 512 + c) * 9;
    float w[9];
    float s2 = 0.f;
#pragma unroll
    for (int q = 0; q < 9; q++) { w[q] = wp[q]; s2 += w[q] * w[q]; }
    g_w2t[c * 512 + o] = s2;

#pragma unroll
    for (int py = 0; py < 2; py++) {
        float r0[3], r1[3];
#pragma unroll
        for (int kx = 0; kx < 3; kx++) {
            r0[kx] = (py == 0) ? w[kx]                 : w[kx] + w[3 + kx];
            r1[kx] = (py == 0) ? w[3 + kx] + w[6 + kx] : w[6 + kx];
        }
#pragma unroll
        for (int px = 0; px < 2; px++) {
            float v[4];
            v[0] = (px == 0) ? r0[0] : r0[0] + r0[1];
            v[1] = (px == 0) ? r0[1] + r0[2] : r0[2];
            v[2] = (px == 0) ? r1[0] : r1[0] + r1[1];
            v[3] = (px == 0) ? r1[1] + r1[2] : r1[2];
            int p = py * 2 + px;
            size_t kb = ((size_t)p * 512 + o) * 2048 + c * 4;
#pragma unroll
            for (int tap = 0; tap < 4; tap++)
                g_wh[kb + tap] = __float2half_rn(v[tap]);
        }
    }
}

// ---------------------------------------------------------------------------
// d[b][o] = rsqrt( sum_c smod[b][c]^2 * W2[o][c] + 1e-8 )
__global__ void k_demod() {
    __shared__ float s2[512];
    int b = blockIdx.y;
    int o = blockIdx.x * 256 + threadIdx.x;
    {
        float a = g_smod[b * 512 + threadIdx.x];
        float bv = g_smod[b * 512 + threadIdx.x + 256];
        s2[threadIdx.x] = a * a;
        s2[threadIdx.x + 256] = bv * bv;
    }
    __syncthreads();
    float acc = 1e-8f;
#pragma unroll 4
    for (int c = 0; c < 512; c++)
        acc += s2[c] * g_w2t[c * 512 + o];
    g_d[b * 512 + o] = rsqrtf(acc);
}

// ---------------------------------------------------------------------------
// xs[b][c][pix] = fp16( x[b][c][pix] * smod[b][c] ); also resets work counter
__global__ void k_xsplit(const float* __restrict__ x) {
    if (blockIdx.x == 0 && threadIdx.x == 0) g_ctr = GRID_MMA;
    int i = blockIdx.x * 256 + threadIdx.x;      // 1,048,576 threads
    int e0 = i * 4;
    int b = e0 >> 19;
    int c = (e0 >> 10) & 511;
    float s = g_smod[b * 512 + c];
    float4 v = *(const float4*)(x + e0);
    __half2 h0 = __floats2half2_rn(v.x * s, v.y * s);
    __half2 h1 = __floats2half2_rn(v.z * s, v.w * s);
    uint2 pk;
    pk.x = *(uint32_t*)&h0;
    pk.y = *(uint32_t*)&h1;
    *(uint2*)((char*)g_xs + (size_t)e0 * 2) = pk;
}

// ---------------------------------------------------------------------------
// Persistent tensor-core implicit-GEMM conv via mma.sync (fp16 in, fp32 acc):
// per (b,p): D[o][n] = sum_k Weff[o][k] * Xg[n][k]
// CTA tile 128o x 128n, KC=64 double-buffered, atomic work queue over 1024
// tiles. Per chunk: W via cp.async, X gathered in 2 register batches
// interleaved with the 4 MMA sub-steps; one __syncthreads per chunk.
// smem: buf = W(18432) + X(18432) = 36864; two bufs = 73728.
// Epilogue reuses buf region as float Ds[128][132].
#define SMEM_REQ 73728

__global__ void __launch_bounds__(256, 2) k_mma(const float* __restrict__ noise,
                                                const float* __restrict__ bias,
                                                float* __restrict__ out) {
    extern __shared__ __align__(16) char smem_raw[];
    __shared__ int s_tile;
    char* abase = smem_raw;
    uint32_t base = smem_u32(smem_raw);

    const int tid = threadIdx.x;
    const int wid = tid >> 5;
    const int lane = tid & 31;

    // thread-invariant constants
    const int nn = tid & 127;        // X-tile row (n local)
    const int khalf = tid >> 7;      // 0/1
    const int wrow = tid >> 1;       // W row pair base (2 rows/thread? -> 4 segs)
    const int wseg = tid & 1;        // see staging: row = tid>>1? recomputed below
    (void)wrow; (void)wseg;
    const int moff = (wid & 1) * 64;
    const int noff = (wid >> 1) * 32;
    const uint32_t aoff = (uint32_t)((moff + (lane & 15)) * LDR + ((lane >> 4) * 8) * 2);
    const uint32_t boff = (uint32_t)((noff + (lane & 7) + ((lane >> 4) << 3)) * LDR
                                     + (((lane >> 3) & 1) * 8) * 2);

    int tile = blockIdx.x;
    while (tile < NTILES) {
        // ---- decompose tile ----
        int nxt = tile & 7;
        int oyt = (tile >> 3) & 3;
        int bp  = tile >> 5;
        int b = bp >> 2, p = bp & 3;
        int py = p >> 1, px = p & 1;
        int obase = oyt * 128;
        int ybase4 = nxt * 4;

        // ---- per-tile gather constants ----
        int yb = ybase4 + (nn >> 5);
        int xb = nn & 31;
        int offt[4];
        unsigned vt[4];
#pragma unroll
        for (int j = 0; j < 2; j++)
#pragma unroll
            for (int i = 0; i < 2; i++) {
                int tap = j * 2 + i;
                int yy = yb + j - 1 + py;
                int xx = xb + i - 1 + px;
                vt[tap] = ((unsigned)yy < 32u) && ((unsigned)xx < 32u);
                offt[tap] = yy * 32 + xx;
            }
        const unsigned short* xbase16 =
            (const unsigned short*)g_xs + ((size_t)b << 19);   // [c][pix]
        const __half* gw = g_wh + ((size_t)(p * 512 + obase)) * 2048;

        float acc[16][4];
#pragma unroll
        for (int q = 0; q < 16; q++)
#pragma unroll
            for (int r = 0; r < 4; r++) acc[q][r] = 0.f;

        // ---- prologue: stage chunk 0 into buf0 ----
        {
#pragma unroll
            for (int s = 0; s < 4; s++) {
                int opid = tid + 256 * s;           // 1024 x 16B
                int row = opid >> 3, seg = opid & 7;
                CP_ASYNC16(base + row * LDR + seg * 16,
                           gw + (size_t)row * 2048 + seg * 8);
            }
            CP_COMMIT();
            char* xdst = abase + 18432;
#pragma unroll
            for (int q = 0; q < 8; q++) {
                int cl = khalf + 2 * q;
                const unsigned short* xc = xbase16 + ((size_t)cl << 10);
                unsigned u0 = vt[0] ? (unsigned)xc[offt[0]] : 0u;
                unsigned u1 = vt[1] ? (unsigned)xc[offt[1]] : 0u;
                unsigned u2 = vt[2] ? (unsigned)xc[offt[2]] : 0u;
                unsigned u3 = vt[3] ? (unsigned)xc[offt[3]] : 0u;
                *(uint2*)(xdst + nn * LDR + cl * 8) =
                    make_uint2(u0 | (u1 << 16), u2 | (u3 << 16));
            }
            CP_WAIT0();
            __syncthreads();
        }

        // ---- main pipelined loop (32 chunks of K=64) ----
        for (int kc = 0; kc < NCHUNKS; kc++) {
            int bf = kc & 1;
            int nb = bf ^ 1;
            bool have_next = (kc + 1 < NCHUNKS);
            int kn = kc + 1;
            uint32_t wS = base + bf * 36864;
            uint32_t xS = wS + 18432;
            char* xdst = abase + nb * 36864 + 18432;

            // 1) W cp.async for next chunk
            if (have_next) {
                uint32_t wdst = base + nb * 36864;
#pragma unroll
                for (int s = 0; s < 4; s++) {
                    int opid = tid + 256 * s;
                    int row = opid >> 3, seg = opid & 7;
                    CP_ASYNC16(wdst + row * LDR + seg * 16,
                               gw + (size_t)row * 2048 + kn * 64 + seg * 8);
                }
            }
            CP_COMMIT();

            // 2) gather first half of next X (cl 0..7)
            uint2 gx[4];
            if (have_next) {
#pragma unroll
                for (int q = 0; q < 4; q++) {
                    int cl = khalf + 2 * q;
                    const unsigned short* xc = xbase16 + ((size_t)(kn * 16 + cl) << 10);
                    unsigned u0 = vt[0] ? (unsigned)__ldg(xc + offt[0]) : 0u;
                    unsigned u1 = vt[1] ? (unsigned)__ldg(xc + offt[1]) : 0u;
                    unsigned u2 = vt[2] ? (unsigned)__ldg(xc + offt[2]) : 0u;
                    unsigned u3 = vt[3] ? (unsigned)__ldg(xc + offt[3]) : 0u;
                    gx[q] = make_uint2(u0 | (u1 << 16), u2 | (u3 << 16));
                }
            }

            // 3) MMA sub-steps ks=0,1
#pragma unroll
            for (int ks = 0; ks < 2; ks++) {
                uint32_t a[4][4], bb[2][4];
#pragma unroll
                for (int mi = 0; mi < 4; mi++)
                    LDMATRIX_X4(a[mi], wS + aoff + ks * 32 + mi * 16 * LDR);
#pragma unroll
                for (int nf = 0; nf < 2; nf++)
                    LDMATRIX_X4(bb[nf], xS + boff + ks * 32 + nf * 16 * LDR);
#pragma unroll
                for (int mi = 0; mi < 4; mi++)
#pragma unroll
                    for (int ni = 0; ni < 4; ni++)
                        MMA16816(acc[mi * 4 + ni], a[mi],
                                 bb[ni >> 1][(ni & 1) * 2], bb[ni >> 1][(ni & 1) * 2 + 1]);
            }

            // 4) land first half, gather second half (cl 8..15)
            if (have_next) {
#pragma unroll
                for (int q = 0; q < 4; q++) {
                    int cl = khalf + 2 * q;
                    *(uint2*)(xdst + nn * LDR + cl * 8) = gx[q];
                }
#pragma unroll
                for (int q = 0; q < 4; q++) {
                    int cl = 8 + khalf + 2 * q;
                    const unsigned short* xc = xbase16 + ((size_t)(kn * 16 + cl) << 10);
                    unsigned u0 = vt[0] ? (unsigned)__ldg(xc + offt[0]) : 0u;
                    unsigned u1 = vt[1] ? (unsigned)__ldg(xc + offt[1]) : 0u;
                    unsigned u2 = vt[2] ? (unsigned)__ldg(xc + offt[2]) : 0u;
                    unsigned u3 = vt[3] ? (unsigned)__ldg(xc + offt[3]) : 0u;
                    gx[q] = make_uint2(u0 | (u1 << 16), u2 | (u3 << 16));
                }
            }

            // 5) MMA sub-steps ks=2,3
#pragma unroll
            for (int ks = 2; ks < 4; ks++) {
                uint32_t a[4][4], bb[2][4];
#pragma unroll
                for (int mi = 0; mi < 4; mi++)
                    LDMATRIX_X4(a[mi], wS + aoff + ks * 32 + mi * 16 * LDR);
#pragma unroll
                for (int nf = 0; nf < 2; nf++)
                    LDMATRIX_X4(bb[nf], xS + boff + ks * 32 + nf * 16 * LDR);
#pragma unroll
                for (int mi = 0; mi < 4; mi++)
#pragma unroll
                    for (int ni = 0; ni < 4; ni++)
                        MMA16816(acc[mi * 4 + ni], a[mi],
                                 bb[ni >> 1][(ni & 1) * 2], bb[ni >> 1][(ni & 1) * 2 + 1]);
            }

            // 6) land second half, wait W, one barrier
            if (have_next) {
#pragma unroll
                for (int q = 0; q < 4; q++) {
                    int cl = 8 + khalf + 2 * q;
                    *(uint2*)(xdst + nn * LDR + cl * 8) = gx[q];
                }
            }
            CP_WAIT0();
            __syncthreads();
        }

        // ---- epilogue: accums -> smem -> fused coalesced store ----
        {
            float* Ds = (float*)abase;
            int g = lane >> 2, t4 = lane & 3;
#pragma unroll
            for (int mi = 0; mi < 4; mi++)
#pragma unroll
                for (int ni = 0; ni < 4; ni++) {
                    int row0 = moff + mi * 16 + g;
                    int col = noff + ni * 8 + t4 * 2;
                    float* ap = acc[mi * 4 + ni];
                    *(float2*)&Ds[row0 * 132 + col]       = make_float2(ap[0], ap[1]);
                    *(float2*)&Ds[(row0 + 8) * 132 + col] = make_float2(ap[2], ap[3]);
                }
            __syncthreads();

#pragma unroll 4
            for (int it = 0; it < 64; it++) {
                int pi = wid * 64 + it;
                int r2 = pi >> 2;            // o local
                int y = pi & 3;              // y local
                int o = obase + r2;
                float a = Ds[r2 * 132 + y * 32 + lane];
                float dv = g_d[b * 512 + o];
                float bv = bias[o];
                int oy = 2 * (ybase4 + y) + py;
                int ox = 2 * lane + px;
                float v = a * dv + bv + noise[b * 4096 + oy * 64 + ox];
                v = (v >= 0.f) ? v : 0.2f * v;
                out[((size_t)(b * 512 + o) << 12) + oy * 64 + ox] = v;
            }
        }

        // ---- grab next tile (all threads must agree) ----
        __syncthreads();                     // Ds reads done before buf reuse
        if (tid == 0) s_tile = (int)atomicAdd(&g_ctr, 1u);
        __syncthreads();
        tile = s_tile;
    }
}

// ---------------------------------------------------------------------------
extern "C" void kernel_launch(void* const* d_in, const int* in_sizes, int n_in,
                              void* d_out, int out_size) {
    const float* x      = (const float*)d_in[0];
    const float* style  = (const float*)d_in[1];
    const float* noise  = (const float*)d_in[2];
    const float* conv_w = (const float*)d_in[3];
    const float* fc_w   = (const float*)d_in[4];
    const float* fc_b   = (const float*)d_in[5];
    const float* bias   = (const float*)d_in[6];
    float* out = (float*)d_out;

    cudaFuncSetAttribute(k_mma, cudaFuncAttributeMaxDynamicSharedMemorySize, SMEM_REQ);

    k_style<<<8, 512>>>(style, fc_w, fc_b);
    k_weff<<<1024, 256>>>(conv_w);
    k_demod<<<dim3(2, 8), 256>>>();
    k_xsplit<<<4096, 256>>>(x);
    k_mma<<<GRID_MMA, 256, SMEM_REQ>>>(noise, bias, out);
}